// round 2
// baseline (speedup 1.0000x reference)
#include <cuda_runtime.h>

#define DIM 64
#define KB 4
#define BATCH 16
#define HIN 256
#define WIN 256
#define HO 127
#define WO 127

#define COG 8        // couts per block
#define IN_H 35      // 16*2+3
#define IN_W 131     // 64*2+3
#define IN_STRIDE 133

__device__ float g_pooled[BATCH * DIM];
__device__ float g_att[BATCH * KB];
__device__ float g_aggb[BATCH * DIM];
__device__ float g_aggw[BATCH * DIM * DIM * 25];   // [b][o][cin][tap], 6.55 MB

// ---------------------------------------------------------------- pool
__global__ void pool_kernel(const float* __restrict__ x) {
    int bc = blockIdx.x;                       // b*64 + c
    const float4* p = (const float4*)(x + (size_t)bc * HIN * WIN);
    float s = 0.f;
    for (int i = threadIdx.x; i < HIN * WIN / 4; i += 256) {
        float4 v = p[i];
        s += v.x + v.y + v.z + v.w;
    }
    __shared__ float red[256];
    red[threadIdx.x] = s;
    __syncthreads();
    for (int off = 128; off > 0; off >>= 1) {
        if (threadIdx.x < off) red[threadIdx.x] += red[threadIdx.x + off];
        __syncthreads();
    }
    if (threadIdx.x == 0) g_pooled[bc] = red[0] * (1.f / (HIN * WIN));
}

// ---------------------------------------------------------------- attention + agg_b
__global__ void att_kernel(const float* __restrict__ fc1_w, const float* __restrict__ fc1_b,
                           const float* __restrict__ fc2_w, const float* __restrict__ fc2_b,
                           const float* __restrict__ bias) {
    __shared__ float s_att[BATCH * KB];
    int tid = threadIdx.x;
    if (tid < BATCH) {
        int b = tid;
        float a[KB];
        #pragma unroll
        for (int k = 0; k < KB; k++) {
            float s = fc1_b[k];
            for (int c = 0; c < DIM; c++) s += g_pooled[b * DIM + c] * fc1_w[k * DIM + c];
            a[k] = fmaxf(s, 0.f);
        }
        float lg[KB];
        float m = -1e30f;
        #pragma unroll
        for (int j = 0; j < KB; j++) {
            float s = fc2_b[j];
            #pragma unroll
            for (int k = 0; k < KB; k++) s += a[k] * fc2_w[j * KB + k];
            lg[j] = s;
            m = fmaxf(m, s);
        }
        float den = 0.f;
        #pragma unroll
        for (int j = 0; j < KB; j++) { lg[j] = expf(lg[j] - m); den += lg[j]; }
        float inv = 1.f / den;
        #pragma unroll
        for (int j = 0; j < KB; j++) {
            float v = lg[j] * inv;
            s_att[b * KB + j] = v;
            g_att[b * KB + j] = v;
        }
    }
    __syncthreads();
    for (int i = tid; i < BATCH * DIM; i += blockDim.x) {
        int b = i / DIM, o = i - b * DIM;
        float s = 0.f;
        #pragma unroll
        for (int k = 0; k < KB; k++) s += s_att[b * KB + k] * bias[k * DIM + o];
        g_aggb[i] = s;
    }
}

// ---------------------------------------------------------------- agg_w mix + w_ret output
__global__ void aggw_kernel(const float* __restrict__ weight, float* __restrict__ out_wret) {
    int idx = blockIdx.x * blockDim.x + threadIdx.x;
    const int PER_B = DIM * DIM * 25;   // 102400
    if (idx >= BATCH * PER_B) return;
    int b = idx / PER_B, r = idx - b * PER_B;
    float s = 0.f;
    #pragma unroll
    for (int k = 0; k < KB; k++) s += g_att[b * KB + k] * weight[k * PER_B + r];
    g_aggw[idx] = s;
    int o = r / (DIM * 25);
    int i = (r / 25) % DIM;
    int t = r % 25;
    // w_ret[(b*64+o), t, i]
    out_wret[((size_t)(b * DIM + o) * 25 + t) * DIM + i] = s;
}

// ---------------------------------------------------------------- per-sample conv
// Block: 64(x) x 16(y) output tile, 8 couts. 256 threads (16x16), each thread
// 4 x-strided pixels x 8 couts = 32 accumulators.
__global__ __launch_bounds__(256) void conv_kernel(const float* __restrict__ x,
                                                   float* __restrict__ out) {
    __shared__ float s_in[IN_H * IN_STRIDE];
    __shared__ float s_w[COG * 25];

    int tid = threadIdx.x;
    int tx = tid & 15, ty = tid >> 4;
    int bx = blockIdx.x, by = blockIdx.y;
    int b = blockIdx.z >> 3, cg = blockIdx.z & 7;

    int iy0 = by * 32 - 1;
    int ix0 = bx * 128 - 1;

    float acc[COG][4];
    #pragma unroll
    for (int c = 0; c < COG; c++)
        #pragma unroll
        for (int p = 0; p < 4; p++) acc[c][p] = 0.f;

    const float* xb = x + (size_t)b * DIM * HIN * WIN;

    for (int cin = 0; cin < DIM; cin++) {
        __syncthreads();
        const float* xp = xb + cin * HIN * WIN;
        for (int i = tid; i < IN_H * IN_W; i += 256) {
            int r = i / IN_W, c = i - r * IN_W;
            int iy = iy0 + r, ix = ix0 + c;
            float v = 0.f;
            if ((unsigned)iy < HIN && (unsigned)ix < WIN) v = xp[iy * WIN + ix];
            s_in[r * IN_STRIDE + c] = v;
        }
        if (tid < COG * 25) {
            int co = tid / 25, t = tid - co * 25;
            s_w[tid] = g_aggw[((size_t)(b * DIM + cg * COG + co) * DIM + cin) * 25 + t];
        }
        __syncthreads();

        #pragma unroll
        for (int ky = 0; ky < 5; ky++) {
            int rb = (2 * ty + ky) * IN_STRIDE + 2 * tx;
            #pragma unroll
            for (int kx = 0; kx < 5; kx++) {
                float v0 = s_in[rb + kx];
                float v1 = s_in[rb + kx + 32];
                float v2 = s_in[rb + kx + 64];
                float v3 = s_in[rb + kx + 96];
                int t = ky * 5 + kx;
                #pragma unroll
                for (int c = 0; c < COG; c++) {
                    float wv = s_w[c * 25 + t];
                    acc[c][0] += v0 * wv;
                    acc[c][1] += v1 * wv;
                    acc[c][2] += v2 * wv;
                    acc[c][3] += v3 * wv;
                }
            }
        }
    }

    int oy = by * 16 + ty;
    if (oy < HO) {
        #pragma unroll
        for (int c = 0; c < COG; c++) {
            int co = cg * COG + c;
            float bv = g_aggb[b * DIM + co];
            float* op = out + ((size_t)(b * DIM + co)) * HO * WO + oy * WO;
            #pragma unroll
            for (int p = 0; p < 4; p++) {
                int ox = bx * 64 + tx + 16 * p;
                if (ox < WO) op[ox] = acc[c][p] + bv;
            }
        }
    }
}

// ---------------------------------------------------------------- launch
extern "C" void kernel_launch(void* const* d_in, const int* in_sizes, int n_in,
                              void* d_out, int out_size) {
    const float* x     = (const float*)d_in[0];
    const float* fc1_w = (const float*)d_in[1];
    const float* fc1_b = (const float*)d_in[2];
    const float* fc2_w = (const float*)d_in[3];
    const float* fc2_b = (const float*)d_in[4];
    const float* weight = (const float*)d_in[5];
    const float* bias  = (const float*)d_in[6];

    float* out = (float*)d_out;
    float* wret = out + (size_t)BATCH * DIM * HO * WO;   // 16,516,096 floats in

    pool_kernel<<<BATCH * DIM, 256>>>(x);
    att_kernel<<<1, 64>>>(fc1_w, fc1_b, fc2_w, fc2_b, bias);
    aggw_kernel<<<(BATCH * DIM * DIM * 25 + 255) / 256, 256>>>(weight, wret);
    conv_kernel<<<dim3(2, 8, BATCH * COG), 256>>>(x, out);
}

// round 3
// speedup vs baseline: 1.0423x; 1.0423x over previous
#include <cuda_runtime.h>
#include <cstdint>

#define DIM 64
#define KB 4
#define BATCH 16
#define HIN 256
#define WIN 256
#define HO 127
#define WO 127

#define COG 8        // couts per block
#define IN_H 35      // 16*2+3
#define IN_W 131     // 64*2+3
#define PL_W 66      // ceil(131/2) columns per parity plane
#define PL_STRIDE 72 // 2*72 mod 32 == 16 -> warp's two rows hit disjoint bank halves

__device__ float g_pooled[BATCH * DIM];
__device__ float g_att[BATCH * KB];
__device__ float g_aggb[BATCH * DIM];
__device__ float g_aggw[BATCH * DIM * DIM * 25];   // [b][o][cin][tap]

#define FMA_F32X2(acc, a, b) \
    asm volatile("fma.rn.f32x2 %0, %1, %2, %0;" : "+l"(acc) : "l"(a), "l"(b))
#define PACK_DUP_F32X2(out, v) \
    asm volatile("mov.b64 %0, {%1, %1};" : "=l"(out) : "r"(__float_as_uint(v)))

// ---------------------------------------------------------------- pool
__global__ void pool_kernel(const float* __restrict__ x) {
    int bc = blockIdx.x;                       // b*64 + c
    const float4* p = (const float4*)(x + (size_t)bc * HIN * WIN);
    float s = 0.f;
    for (int i = threadIdx.x; i < HIN * WIN / 4; i += 256) {
        float4 v = p[i];
        s += v.x + v.y + v.z + v.w;
    }
    __shared__ float red[256];
    red[threadIdx.x] = s;
    __syncthreads();
    for (int off = 128; off > 0; off >>= 1) {
        if (threadIdx.x < off) red[threadIdx.x] += red[threadIdx.x + off];
        __syncthreads();
    }
    if (threadIdx.x == 0) g_pooled[bc] = red[0] * (1.f / (HIN * WIN));
}

// ---------------------------------------------------------------- attention + agg_b
__global__ void att_kernel(const float* __restrict__ fc1_w, const float* __restrict__ fc1_b,
                           const float* __restrict__ fc2_w, const float* __restrict__ fc2_b,
                           const float* __restrict__ bias) {
    __shared__ float s_att[BATCH * KB];
    int tid = threadIdx.x;
    if (tid < BATCH) {
        int b = tid;
        float a[KB];
        #pragma unroll
        for (int k = 0; k < KB; k++) {
            float s = fc1_b[k];
            for (int c = 0; c < DIM; c++) s += g_pooled[b * DIM + c] * fc1_w[k * DIM + c];
            a[k] = fmaxf(s, 0.f);
        }
        float lg[KB];
        float m = -1e30f;
        #pragma unroll
        for (int j = 0; j < KB; j++) {
            float s = fc2_b[j];
            #pragma unroll
            for (int k = 0; k < KB; k++) s += a[k] * fc2_w[j * KB + k];
            lg[j] = s;
            m = fmaxf(m, s);
        }
        float den = 0.f;
        #pragma unroll
        for (int j = 0; j < KB; j++) { lg[j] = expf(lg[j] - m); den += lg[j]; }
        float inv = 1.f / den;
        #pragma unroll
        for (int j = 0; j < KB; j++) {
            float v = lg[j] * inv;
            s_att[b * KB + j] = v;
            g_att[b * KB + j] = v;
        }
    }
    __syncthreads();
    for (int i = tid; i < BATCH * DIM; i += blockDim.x) {
        int b = i / DIM, o = i - b * DIM;
        float s = 0.f;
        #pragma unroll
        for (int k = 0; k < KB; k++) s += s_att[b * KB + k] * bias[k * DIM + o];
        g_aggb[i] = s;
    }
}

// ---------------------------------------------------------------- agg_w mix + w_ret output
__global__ void aggw_kernel(const float* __restrict__ weight, float* __restrict__ out_wret) {
    int idx = blockIdx.x * blockDim.x + threadIdx.x;
    const int PER_B = DIM * DIM * 25;   // 102400
    if (idx >= BATCH * PER_B) return;
    int b = idx / PER_B, r = idx - b * PER_B;
    float s = 0.f;
    #pragma unroll
    for (int k = 0; k < KB; k++) s += g_att[b * KB + k] * weight[k * PER_B + r];
    g_aggw[idx] = s;
    int o = r / (DIM * 25);
    int i = (r / 25) % DIM;
    int t = r % 25;
    out_wret[((size_t)(b * DIM + o) * 25 + t) * DIM + i] = s;
}

// ---------------------------------------------------------------- per-sample conv
// Block: 64(x) x 16(y) output tile, 8 couts. 256 threads (16x16).
// Each thread: 4 x-strided pixels x 4 cout-pairs, packed f32x2 accumulators.
// Input smem split by column parity -> conflict-free stride-2 reads.
__global__ __launch_bounds__(256) void conv_kernel(const float* __restrict__ x,
                                                   float* __restrict__ out) {
    __shared__ float s_even[IN_H * PL_STRIDE];
    __shared__ float s_odd[IN_H * PL_STRIDE];
    __shared__ __align__(8) float s_w[25 * COG];   // [tap][cout] -> cout pairs contiguous

    int tid = threadIdx.x;
    int tx = tid & 15, ty = tid >> 4;
    int bx = blockIdx.x, by = blockIdx.y;
    int b = blockIdx.z >> 3, cg = blockIdx.z & 7;

    int iy0 = by * 32 - 1;
    int ix0 = bx * 128 - 1;

    uint64_t acc[4][4];   // [cout_pair][pixel] packed f32x2
    #pragma unroll
    for (int cp = 0; cp < 4; cp++)
        #pragma unroll
        for (int p = 0; p < 4; p++) acc[cp][p] = 0ull;

    const float* xb = x + (size_t)b * DIM * HIN * WIN;
    const float* pe_base = s_even + 2 * ty * PL_STRIDE + tx;
    const float* po_base = s_odd  + 2 * ty * PL_STRIDE + tx;

    for (int cin = 0; cin < DIM; cin++) {
        __syncthreads();
        const float* xp = xb + cin * HIN * WIN;
        for (int i = tid; i < IN_H * IN_W; i += 256) {
            int r = i / IN_W, c = i - r * IN_W;
            int iy = iy0 + r, ix = ix0 + c;
            float v = 0.f;
            if ((unsigned)iy < HIN && (unsigned)ix < WIN) v = xp[iy * WIN + ix];
            float* dst = (c & 1) ? s_odd : s_even;
            dst[r * PL_STRIDE + (c >> 1)] = v;
        }
        if (tid < COG * 25) {
            int co = tid / 25, t = tid - co * 25;
            s_w[t * COG + co] =
                g_aggw[((size_t)(b * DIM + cg * COG + co) * DIM + cin) * 25 + t];
        }
        __syncthreads();

        #pragma unroll
        for (int ky = 0; ky < 5; ky++) {
            #pragma unroll
            for (int kx = 0; kx < 5; kx++) {
                const float* pl = (kx & 1) ? po_base : pe_base;
                int off = ky * PL_STRIDE + (kx >> 1);
                float v0 = pl[off];
                float v1 = pl[off + 16];
                float v2 = pl[off + 32];
                float v3 = pl[off + 48];
                uint64_t v0p, v1p, v2p, v3p;
                PACK_DUP_F32X2(v0p, v0);
                PACK_DUP_F32X2(v1p, v1);
                PACK_DUP_F32X2(v2p, v2);
                PACK_DUP_F32X2(v3p, v3);
                int t = ky * 5 + kx;
                #pragma unroll
                for (int cp = 0; cp < 4; cp++) {
                    uint64_t wpair =
                        *reinterpret_cast<const uint64_t*>(&s_w[t * COG + 2 * cp]);
                    FMA_F32X2(acc[cp][0], v0p, wpair);
                    FMA_F32X2(acc[cp][1], v1p, wpair);
                    FMA_F32X2(acc[cp][2], v2p, wpair);
                    FMA_F32X2(acc[cp][3], v3p, wpair);
                }
            }
        }
    }

    int oy = by * 16 + ty;
    if (oy < HO) {
        #pragma unroll
        for (int cp = 0; cp < 4; cp++) {
            #pragma unroll
            for (int h = 0; h < 2; h++) {
                int co = cg * COG + 2 * cp + h;
                float bv = g_aggb[b * DIM + co];
                float* op = out + ((size_t)(b * DIM + co)) * HO * WO + oy * WO;
                #pragma unroll
                for (int p = 0; p < 4; p++) {
                    int ox = bx * 64 + tx + 16 * p;
                    if (ox < WO) {
                        uint32_t lo = (uint32_t)(acc[cp][p] & 0xFFFFFFFFull);
                        uint32_t hi = (uint32_t)(acc[cp][p] >> 32);
                        float av = h ? __uint_as_float(hi) : __uint_as_float(lo);
                        op[ox] = av + bv;
                    }
                }
            }
        }
    }
}

// ---------------------------------------------------------------- launch
extern "C" void kernel_launch(void* const* d_in, const int* in_sizes, int n_in,
                              void* d_out, int out_size) {
    const float* x     = (const float*)d_in[0];
    const float* fc1_w = (const float*)d_in[1];
    const float* fc1_b = (const float*)d_in[2];
    const float* fc2_w = (const float*)d_in[3];
    const float* fc2_b = (const float*)d_in[4];
    const float* weight = (const float*)d_in[5];
    const float* bias  = (const float*)d_in[6];

    float* out = (float*)d_out;
    float* wret = out + (size_t)BATCH * DIM * HO * WO;

    pool_kernel<<<BATCH * DIM, 256>>>(x);
    att_kernel<<<1, 64>>>(fc1_w, fc1_b, fc2_w, fc2_b, bias);
    aggw_kernel<<<(BATCH * DIM * DIM * 25 + 255) / 256, 256>>>(weight, wret);
    conv_kernel<<<dim3(2, 8, BATCH * COG), 256>>>(x, out);
}

// round 4
// speedup vs baseline: 1.0458x; 1.0034x over previous
#include <cuda_runtime.h>
#include <cstdint>

#define DIM 64
#define KB 4
#define BATCH 16
#define HIN 256
#define WIN 256
#define HO 127
#define WO 127

#define COG 8        // couts per block
#define IN_H 35      // 16*2+3
#define IN_W 131     // 64*2+3
#define PL_W 66      // ceil(131/2) columns per parity plane
#define PL_STRIDE 72 // 2*72 mod 32 == 16 -> warp's two rows hit disjoint bank halves

__device__ float g_pooled[BATCH * DIM];
__device__ float g_att[BATCH * KB];
__device__ float g_aggb[BATCH * DIM];
__device__ float g_aggw[BATCH * DIM * DIM * 25];   // [b][o][cin][tap]

#define FMA_F32X2(acc, a, b) \
    asm volatile("fma.rn.f32x2 %0, %1, %2, %0;" : "+l"(acc) : "l"(a), "l"(b))
#define PACK_DUP_F32X2(out, v) \
    asm volatile("mov.b64 %0, {%1, %1};" : "=l"(out) : "r"(__float_as_uint(v)))

// ---------------------------------------------------------------- pool
__global__ void pool_kernel(const float* __restrict__ x) {
    int bc = blockIdx.x;                       // b*64 + c
    const float4* p = (const float4*)(x + (size_t)bc * HIN * WIN);
    float s = 0.f;
    for (int i = threadIdx.x; i < HIN * WIN / 4; i += 256) {
        float4 v = p[i];
        s += v.x + v.y + v.z + v.w;
    }
    __shared__ float red[256];
    red[threadIdx.x] = s;
    __syncthreads();
    for (int off = 128; off > 0; off >>= 1) {
        if (threadIdx.x < off) red[threadIdx.x] += red[threadIdx.x + off];
        __syncthreads();
    }
    if (threadIdx.x == 0) g_pooled[bc] = red[0] * (1.f / (HIN * WIN));
}

// ---------------------------------------------------------------- attention + agg_b
__global__ void att_kernel(const float* __restrict__ fc1_w, const float* __restrict__ fc1_b,
                           const float* __restrict__ fc2_w, const float* __restrict__ fc2_b,
                           const float* __restrict__ bias) {
    __shared__ float s_att[BATCH * KB];
    int tid = threadIdx.x;
    if (tid < BATCH) {
        int b = tid;
        float a[KB];
        #pragma unroll
        for (int k = 0; k < KB; k++) {
            float s = fc1_b[k];
            for (int c = 0; c < DIM; c++) s += g_pooled[b * DIM + c] * fc1_w[k * DIM + c];
            a[k] = fmaxf(s, 0.f);
        }
        float lg[KB];
        float m = -1e30f;
        #pragma unroll
        for (int j = 0; j < KB; j++) {
            float s = fc2_b[j];
            #pragma unroll
            for (int k = 0; k < KB; k++) s += a[k] * fc2_w[j * KB + k];
            lg[j] = s;
            m = fmaxf(m, s);
        }
        float den = 0.f;
        #pragma unroll
        for (int j = 0; j < KB; j++) { lg[j] = expf(lg[j] - m); den += lg[j]; }
        float inv = 1.f / den;
        #pragma unroll
        for (int j = 0; j < KB; j++) {
            float v = lg[j] * inv;
            s_att[b * KB + j] = v;
            g_att[b * KB + j] = v;
        }
    }
    __syncthreads();
    for (int i = tid; i < BATCH * DIM; i += blockDim.x) {
        int b = i / DIM, o = i - b * DIM;
        float s = 0.f;
        #pragma unroll
        for (int k = 0; k < KB; k++) s += s_att[b * KB + k] * bias[k * DIM + o];
        g_aggb[i] = s;
    }
}

// ---------------------------------------------------------------- agg_w mix + w_ret output
__global__ void aggw_kernel(const float* __restrict__ weight, float* __restrict__ out_wret) {
    int idx = blockIdx.x * blockDim.x + threadIdx.x;
    const int PER_B = DIM * DIM * 25;   // 102400
    if (idx >= BATCH * PER_B) return;
    int b = idx / PER_B, r = idx - b * PER_B;
    float s = 0.f;
    #pragma unroll
    for (int k = 0; k < KB; k++) s += g_att[b * KB + k] * weight[k * PER_B + r];
    g_aggw[idx] = s;
    int o = r / (DIM * 25);
    int i = (r / 25) % DIM;
    int t = r % 25;
    out_wret[((size_t)(b * DIM + o) * 25 + t) * DIM + i] = s;
}

// ---------------------------------------------------------------- per-sample conv
// Block: 64(x) x 16(y) output tile, 8 couts. 256 threads (16x16).
// Each thread: 4 x-strided pixels x 4 cout-pairs, packed f32x2 accumulators.
// Input smem split by column parity -> conflict-free stride-2 reads.
__global__ __launch_bounds__(256) void conv_kernel(const float* __restrict__ x,
                                                   float* __restrict__ out) {
    __shared__ float s_even[IN_H * PL_STRIDE];
    __shared__ float s_odd[IN_H * PL_STRIDE];
    __shared__ __align__(8) float s_w[25 * COG];   // [tap][cout] -> cout pairs contiguous

    int tid = threadIdx.x;
    int tx = tid & 15, ty = tid >> 4;
    int bx = blockIdx.x, by = blockIdx.y;
    int b = blockIdx.z >> 3, cg = blockIdx.z & 7;

    int iy0 = by * 32 - 1;
    int ix0 = bx * 128 - 1;

    uint64_t acc[4][4];   // [cout_pair][pixel] packed f32x2
    #pragma unroll
    for (int cp = 0; cp < 4; cp++)
        #pragma unroll
        for (int p = 0; p < 4; p++) acc[cp][p] = 0ull;

    const float* xb = x + (size_t)b * DIM * HIN * WIN;
    const float* pe_base = s_even + 2 * ty * PL_STRIDE + tx;
    const float* po_base = s_odd  + 2 * ty * PL_STRIDE + tx;

    for (int cin = 0; cin < DIM; cin++) {
        __syncthreads();
        const float* xp = xb + cin * HIN * WIN;
        for (int i = tid; i < IN_H * IN_W; i += 256) {
            int r = i / IN_W, c = i - r * IN_W;
            int iy = iy0 + r, ix = ix0 + c;
            float v = 0.f;
            if ((unsigned)iy < HIN && (unsigned)ix < WIN) v = xp[iy * WIN + ix];
            float* dst = (c & 1) ? s_odd : s_even;
            dst[r * PL_STRIDE + (c >> 1)] = v;
        }
        if (tid < COG * 25) {
            int co = tid / 25, t = tid - co * 25;
            s_w[t * COG + co] =
                g_aggw[((size_t)(b * DIM + cg * COG + co) * DIM + cin) * 25 + t];
        }
        __syncthreads();

        #pragma unroll
        for (int ky = 0; ky < 5; ky++) {
            #pragma unroll
            for (int kx = 0; kx < 5; kx++) {
                const float* pl = (kx & 1) ? po_base : pe_base;
                int off = ky * PL_STRIDE + (kx >> 1);
                float v0 = pl[off];
                float v1 = pl[off + 16];
                float v2 = pl[off + 32];
                float v3 = pl[off + 48];
                uint64_t v0p, v1p, v2p, v3p;
                PACK_DUP_F32X2(v0p, v0);
                PACK_DUP_F32X2(v1p, v1);
                PACK_DUP_F32X2(v2p, v2);
                PACK_DUP_F32X2(v3p, v3);
                int t = ky * 5 + kx;
                #pragma unroll
                for (int cp = 0; cp < 4; cp++) {
                    uint64_t wpair =
                        *reinterpret_cast<const uint64_t*>(&s_w[t * COG + 2 * cp]);
                    FMA_F32X2(acc[cp][0], v0p, wpair);
                    FMA_F32X2(acc[cp][1], v1p, wpair);
                    FMA_F32X2(acc[cp][2], v2p, wpair);
                    FMA_F32X2(acc[cp][3], v3p, wpair);
                }
            }
        }
    }

    int oy = by * 16 + ty;
    if (oy < HO) {
        #pragma unroll
        for (int cp = 0; cp < 4; cp++) {
            #pragma unroll
            for (int h = 0; h < 2; h++) {
                int co = cg * COG + 2 * cp + h;
                float bv = g_aggb[b * DIM + co];
                float* op = out + ((size_t)(b * DIM + co)) * HO * WO + oy * WO;
                #pragma unroll
                for (int p = 0; p < 4; p++) {
                    int ox = bx * 64 + tx + 16 * p;
                    if (ox < WO) {
                        uint32_t lo = (uint32_t)(acc[cp][p] & 0xFFFFFFFFull);
                        uint32_t hi = (uint32_t)(acc[cp][p] >> 32);
                        float av = h ? __uint_as_float(hi) : __uint_as_float(lo);
                        op[ox] = av + bv;
                    }
                }
            }
        }
    }
}

// ---------------------------------------------------------------- launch
extern "C" void kernel_launch(void* const* d_in, const int* in_sizes, int n_in,
                              void* d_out, int out_size) {
    const float* x     = (const float*)d_in[0];
    const float* fc1_w = (const float*)d_in[1];
    const float* fc1_b = (const float*)d_in[2];
    const float* fc2_w = (const float*)d_in[3];
    const float* fc2_b = (const float*)d_in[4];
    const float* weight = (const float*)d_in[5];
    const float* bias  = (const float*)d_in[6];

    float* out = (float*)d_out;
    float* wret = out + (size_t)BATCH * DIM * HO * WO;

    pool_kernel<<<BATCH * DIM, 256>>>(x);
    att_kernel<<<1, 64>>>(fc1_w, fc1_b, fc2_w, fc2_b, bias);
    aggw_kernel<<<(BATCH * DIM * DIM * 25 + 255) / 256, 256>>>(weight, wret);
    conv_kernel<<<dim3(2, 8, BATCH * COG), 256>>>(x, out);
}

// round 6
// speedup vs baseline: 1.2509x; 1.1960x over previous
#include <cuda_runtime.h>
#include <cstdint>

#define DIM 64
#define KB 4
#define BATCH 16
#define HIN 256
#define WIN 256
#define HO 127
#define WO 127
#define KTOT 1600
#define KC 32
#define CHUNKS 50

#define SA_STRIDE 36                    // words; 36 mod 32 == 4 -> conflict-free frags
#define OFF_A0 0
#define OFF_A1 (256 * SA_STRIDE)        // 9216 words
#define OFF_B0 (2 * 256 * SA_STRIDE)    // 18432
#define OFF_B1 (OFF_B0 + 64 * SA_STRIDE)
#define SMEM_WORDS (OFF_B1 + 64 * SA_STRIDE)   // 23040 words = 92160 B

__device__ float g_xp[BATCH * DIM * 4 * 128 * 128];   // polyphase images (tf32-rounded)
__device__ float g_pooled[BATCH * DIM];
__device__ float g_att[BATCH * KB];
__device__ float g_aggb[BATCH * DIM];
__device__ float g_wg[BATCH * DIM * KTOT];            // mixed weights [b][co][k] (tf32-rounded)
__device__ int   g_ktab[KTOT];

__device__ __forceinline__ float to_tf32(float v) {
    uint32_t u; asm("cvt.rna.tf32.f32 %0, %1;" : "=r"(u) : "f"(v));
    return __uint_as_float(u);
}
__device__ __forceinline__ void mma_tf32(float* d, const uint32_t* a, uint32_t b0, uint32_t b1) {
    asm volatile(
        "mma.sync.aligned.m16n8k8.row.col.f32.tf32.tf32.f32 "
        "{%0,%1,%2,%3}, {%4,%5,%6,%7}, {%8,%9}, {%0,%1,%2,%3};"
        : "+f"(d[0]), "+f"(d[1]), "+f"(d[2]), "+f"(d[3])
        : "r"(a[0]), "r"(a[1]), "r"(a[2]), "r"(a[3]), "r"(b0), "r"(b1));
}

// ------------------------------------------------- k -> (plane, ryo, dx) table
__global__ void ktab_kernel() {
    int k = blockIdx.x * 256 + threadIdx.x;
    if (k >= KTOT) return;
    int cin = k / 25, t = k % 25, ky = t / 5, kx = t % 5;
    int pr = (ky + 1) & 1, pc = (kx + 1) & 1;
    int ryo = (ky - 1) >> 1, dx = (kx - 1) >> 1;
    g_ktab[k] = ((cin * 4 + pr * 2 + pc) << 8) | ((ryo + 1) << 4) | (dx + 1);
}

// ------------------------------------------------- polyphase split + pool
__global__ void prepass_kernel(const float* __restrict__ x) {
    int bc = blockIdx.x;
    const float2* src = (const float2*)(x + (size_t)bc * HIN * WIN);
    float* pl = g_xp + (size_t)bc * 4 * 16384;
    float s = 0.f;
    for (int i = threadIdx.x; i < 128 * 256; i += 256) {
        int iy = i >> 7, hx = i & 127;
        float2 v = src[i];
        s += v.x + v.y;
        int r = iy >> 1, pr = iy & 1;
        pl[(pr * 2 + 0) * 16384 + r * 128 + hx] = to_tf32(v.x);
        pl[(pr * 2 + 1) * 16384 + r * 128 + hx] = to_tf32(v.y);
    }
    __shared__ float red[256];
    red[threadIdx.x] = s;
    __syncthreads();
    for (int off = 128; off > 0; off >>= 1) {
        if (threadIdx.x < off) red[threadIdx.x] += red[threadIdx.x + off];
        __syncthreads();
    }
    if (threadIdx.x == 0) g_pooled[bc] = red[0] * (1.f / (HIN * WIN));
}

// ------------------------------------------------- attention + agg_b
__global__ void att_kernel(const float* __restrict__ fc1_w, const float* __restrict__ fc1_b,
                           const float* __restrict__ fc2_w, const float* __restrict__ fc2_b,
                           const float* __restrict__ bias) {
    __shared__ float s_att[BATCH * KB];
    int tid = threadIdx.x;
    if (tid < BATCH) {
        int b = tid;
        float a[KB];
        #pragma unroll
        for (int k = 0; k < KB; k++) {
            float s = fc1_b[k];
            for (int c = 0; c < DIM; c++) s += g_pooled[b * DIM + c] * fc1_w[k * DIM + c];
            a[k] = fmaxf(s, 0.f);
        }
        float lg[KB], m = -1e30f;
        #pragma unroll
        for (int j = 0; j < KB; j++) {
            float s = fc2_b[j];
            #pragma unroll
            for (int k = 0; k < KB; k++) s += a[k] * fc2_w[j * KB + k];
            lg[j] = s; m = fmaxf(m, s);
        }
        float den = 0.f;
        #pragma unroll
        for (int j = 0; j < KB; j++) { lg[j] = expf(lg[j] - m); den += lg[j]; }
        float inv = 1.f / den;
        #pragma unroll
        for (int j = 0; j < KB; j++) { s_att[b * KB + j] = lg[j] * inv; g_att[b * KB + j] = lg[j] * inv; }
    }
    __syncthreads();
    for (int i = tid; i < BATCH * DIM; i += blockDim.x) {
        int b = i / DIM, o = i - b * DIM;
        float s = 0.f;
        #pragma unroll
        for (int k = 0; k < KB; k++) s += s_att[b * KB + k] * bias[k * DIM + o];
        g_aggb[i] = s;
    }
}

// ------------------------------------------------- weight mix + w_ret
__global__ void aggw_kernel(const float* __restrict__ weight, float* __restrict__ out_wret) {
    int idx = blockIdx.x * blockDim.x + threadIdx.x;
    const int PER_B = DIM * KTOT;
    if (idx >= BATCH * PER_B) return;
    int b = idx / PER_B, r = idx - b * PER_B;
    float s = 0.f;
    #pragma unroll
    for (int k = 0; k < KB; k++) s += g_att[b * KB + k] * weight[k * PER_B + r];
    g_wg[idx] = to_tf32(s);
    int o = r / KTOT, rem = r - o * KTOT;
    int i = rem / 25, t = rem - i * 25;
    out_wret[((size_t)(b * DIM + o) * 25 + t) * DIM + i] = s;   // exact f32
}

// ------------------------------------------------- tf32 mma.sync implicit-GEMM conv
// CTA=(oy-pair, b): D[256px, 64co] = A_im2col[256,1600] x W[64,1600]^T
// 8 warps: warp tile 64px x 32co (wm=wid&3, wn=wid>>2). Double-buffered SMEM.
__global__ __launch_bounds__(256) void conv_mma_kernel(float* __restrict__ out) {
    extern __shared__ float sm[];
    int tid = threadIdx.x, lane = tid & 31, wid = tid >> 5;
    int wm = wid & 3, wn = wid >> 2;
    int oy0 = blockIdx.x * 2, b = blockIdx.y;

    const float* xpb = g_xp + (size_t)b * 256 * 16384;
    const float* wgb = g_wg + (size_t)b * DIM * KTOT;
    int kloc = tid >> 3;     // 0..31  (A stage: one k-row, 32 px)
    int pxo  = tid & 7;
    int bco  = tid >> 2;     // 0..63  (B stage)
    int bkq  = tid & 3;

    float acc[4][4][4];
    #pragma unroll
    for (int mt = 0; mt < 4; mt++)
        #pragma unroll
        for (int nt = 0; nt < 4; nt++)
            #pragma unroll
            for (int r = 0; r < 4; r++) acc[mt][nt][r] = 0.f;

    int g = lane >> 2, cl = lane & 3;

    // ---- stage chunk c into (sA, sB)
    auto stage = [&](int c, float* sA, float* sB) {
        int meta = g_ktab[c * KC + kloc];
        const float* pl = xpb + (meta >> 8) * 16384;
        int ryo = ((meta >> 4) & 15) - 1;
        int dx  = (meta & 15) - 1;
        int ry0 = oy0 + ryo;
        #pragma unroll
        for (int m = 0; m < 32; m++) {
            int px = pxo + 8 * m;
            int q = px >> 7, ox = px & 127;
            int ry = ry0 + q, cx = ox + dx;
            float v = 0.f;
            if ((unsigned)ry < 128u && (unsigned)cx < 128u) v = pl[ry * 128 + cx];
            sA[px * SA_STRIDE + kloc] = v;
        }
        const float4* wr = (const float4*)(wgb + (size_t)bco * KTOT + c * KC + bkq * 8);
        float4 w0 = wr[0], w1 = wr[1];
        float* db = sB + bco * SA_STRIDE + bkq * 8;
        db[0] = w0.x; db[1] = w0.y; db[2] = w0.z; db[3] = w0.w;
        db[4] = w1.x; db[5] = w1.y; db[6] = w1.z; db[7] = w1.w;
    };

    // ---- consume chunk from (sA, sB)
    auto consume = [&](const float* sA, const float* sB) {
        #pragma unroll
        for (int k8 = 0; k8 < 4; k8++) {
            int k0 = k8 * 8;
            uint32_t a[4][4];
            #pragma unroll
            for (int mt = 0; mt < 4; mt++) {
                const float* ba = sA + (wm * 64 + mt * 16 + g) * SA_STRIDE + k0 + cl;
                a[mt][0] = __float_as_uint(ba[0]);
                a[mt][1] = __float_as_uint(ba[8 * SA_STRIDE]);
                a[mt][2] = __float_as_uint(ba[4]);
                a[mt][3] = __float_as_uint(ba[8 * SA_STRIDE + 4]);
            }
            #pragma unroll
            for (int nt = 0; nt < 4; nt++) {
                const float* bb = sB + (wn * 32 + nt * 8 + g) * SA_STRIDE + k0 + cl;
                uint32_t b0 = __float_as_uint(bb[0]);
                uint32_t b1 = __float_as_uint(bb[4]);
                #pragma unroll
                for (int mt = 0; mt < 4; mt++)
                    mma_tf32(acc[mt][nt], a[mt], b0, b1);
            }
        }
    };

    stage(0, sm + OFF_A0, sm + OFF_B0);
    __syncthreads();
    for (int c = 0; c < CHUNKS; c++) {
        float* cA = sm + ((c & 1) ? OFF_A1 : OFF_A0);
        float* cB = sm + ((c & 1) ? OFF_B1 : OFF_B0);
        float* nA = sm + ((c & 1) ? OFF_A0 : OFF_A1);
        float* nB = sm + ((c & 1) ? OFF_B0 : OFF_B1);
        if (c + 1 < CHUNKS) stage(c + 1, nA, nB);
        consume(cA, cB);
        __syncthreads();
    }

    // ---- epilogue
    const float* ab = g_aggb + b * DIM;
    #pragma unroll
    for (int mt = 0; mt < 4; mt++) {
        int pxb = wm * 64 + mt * 16 + g;
        #pragma unroll
        for (int half = 0; half < 2; half++) {
            int px = pxb + half * 8;
            int q = px >> 7, ox = px & 127;
            int oy = oy0 + q;
            if (oy < HO && ox < WO) {
                #pragma unroll
                for (int nt = 0; nt < 4; nt++) {
                    int co = wn * 32 + nt * 8 + cl * 2;
                    float* op = out + ((size_t)(b * DIM + co)) * (HO * WO) + oy * WO + ox;
                    op[0]       = acc[mt][nt][2 * half]     + ab[co];
                    op[HO * WO] = acc[mt][nt][2 * half + 1] + ab[co + 1];
                }
            }
        }
    }
}

// ------------------------------------------------- launch
extern "C" void kernel_launch(void* const* d_in, const int* in_sizes, int n_in,
                              void* d_out, int out_size) {
    const float* x     = (const float*)d_in[0];
    const float* fc1_w = (const float*)d_in[1];
    const float* fc1_b = (const float*)d_in[2];
    const float* fc2_w = (const float*)d_in[3];
    const float* fc2_b = (const float*)d_in[4];
    const float* weight = (const float*)d_in[5];
    const float* bias  = (const float*)d_in[6];

    float* out = (float*)d_out;
    float* wret = out + (size_t)BATCH * DIM * HO * WO;

    ktab_kernel<<<7, 256>>>();
    prepass_kernel<<<BATCH * DIM, 256>>>(x);
    att_kernel<<<1, 64>>>(fc1_w, fc1_b, fc2_w, fc2_b, bias);
    aggw_kernel<<<(BATCH * DIM * KTOT + 255) / 256, 256>>>(weight, wret);

    cudaFuncSetAttribute(conv_mma_kernel, cudaFuncAttributeMaxDynamicSharedMemorySize,
                         SMEM_WORDS * 4);
    conv_mma_kernel<<<dim3(64, BATCH), 256, SMEM_WORDS * 4>>>(out);
}

// round 7
// speedup vs baseline: 2.7135x; 2.1693x over previous
#include <cuda_runtime.h>
#include <cstdint>

#define DIM 64
#define KB 4
#define BATCH 16
#define HIN 256
#define WIN 256
#define HO 127
#define WO 127
#define KTOT 1600
#define KC 32
#define CHUNKS 50
#define PER_B (DIM * KTOT)   // 102400

#define AROW 136             // words per (k,q) source row; data at [4..131], edges 3/132
#define BSTRIDE 36
#define OFF_A0 0
#define OFF_A1 (64 * AROW)            // 8704
#define OFF_B0 (2 * 64 * AROW)        // 17408
#define OFF_B1 (OFF_B0 + 64 * BSTRIDE)
#define OFF_T0 (OFF_B1 + 64 * BSTRIDE)   // 22016
#define OFF_T1 (OFF_T0 + 32)
#define SMEM_WORDS (OFF_T1 + 32)      // 22080 words = 88320 B

__device__ float g_xp[BATCH * DIM * 4 * 128 * 128];   // polyphase images (tf32)
__device__ float g_pooled[BATCH * DIM];
__device__ float g_aggb[BATCH * DIM];
__device__ float g_wg[BATCH * DIM * KTOT];            // mixed weights [b][co][k] (tf32)
__device__ int   g_ktab[KTOT];

__device__ __forceinline__ float to_tf32(float v) {
    uint32_t u; asm("cvt.rna.tf32.f32 %0, %1;" : "=r"(u) : "f"(v));
    return __uint_as_float(u);
}
__device__ __forceinline__ void mma_tf32(float* d, const uint32_t* a, uint32_t b0, uint32_t b1) {
    asm volatile(
        "mma.sync.aligned.m16n8k8.row.col.f32.tf32.tf32.f32 "
        "{%0,%1,%2,%3}, {%4,%5,%6,%7}, {%8,%9}, {%0,%1,%2,%3};"
        : "+f"(d[0]), "+f"(d[1]), "+f"(d[2]), "+f"(d[3])
        : "r"(a[0]), "r"(a[1]), "r"(a[2]), "r"(a[3]), "r"(b0), "r"(b1));
}

// ------------------------------------------------- prepass: polyphase split + pool + ktab
__global__ void prepass_kernel(const float* __restrict__ x) {
    int bc = blockIdx.x;
    if (bc == 0) {
        for (int k = threadIdx.x; k < KTOT; k += 256) {
            int cin = k / 25, t = k % 25, ky = t / 5, kx = t % 5;
            int pr = (ky + 1) & 1, pc = (kx + 1) & 1;
            int ryo = (ky - 1) >> 1, dx = (kx - 1) >> 1;
            g_ktab[k] = ((cin * 4 + pr * 2 + pc) << 8) | ((ryo + 1) << 4) | (dx + 1);
        }
    }
    const float2* src = (const float2*)(x + (size_t)bc * HIN * WIN);
    float* pl = g_xp + (size_t)bc * 4 * 16384;
    float s = 0.f;
    for (int i = threadIdx.x; i < 128 * 256; i += 256) {
        int iy = i >> 7, hx = i & 127;
        float2 v = src[i];
        s += v.x + v.y;
        int r = iy >> 1, pr = iy & 1;
        pl[(pr * 2 + 0) * 16384 + r * 128 + hx] = to_tf32(v.x);
        pl[(pr * 2 + 1) * 16384 + r * 128 + hx] = to_tf32(v.y);
    }
    __shared__ float red[256];
    red[threadIdx.x] = s;
    __syncthreads();
    for (int off = 128; off > 0; off >>= 1) {
        if (threadIdx.x < off) red[threadIdx.x] += red[threadIdx.x + off];
        __syncthreads();
    }
    if (threadIdx.x == 0) g_pooled[bc] = red[0] * (1.f / (HIN * WIN));
}

// ------------------------------------------------- attention (per-block) + weight mix + w_ret + agg_b
__global__ void aggw_kernel(const float* __restrict__ fc1_w, const float* __restrict__ fc1_b,
                            const float* __restrict__ fc2_w, const float* __restrict__ fc2_b,
                            const float* __restrict__ weight, const float* __restrict__ bias,
                            float* __restrict__ out_wret) {
    __shared__ float s_att[KB];
    int b = blockIdx.y, tid = threadIdx.x;
    if (tid == 0) {
        float a[KB];
        #pragma unroll
        for (int k = 0; k < KB; k++) {
            float s = fc1_b[k];
            for (int c = 0; c < DIM; c++) s += g_pooled[b * DIM + c] * fc1_w[k * DIM + c];
            a[k] = fmaxf(s, 0.f);
        }
        float lg[KB], m = -1e30f;
        #pragma unroll
        for (int j = 0; j < KB; j++) {
            float s = fc2_b[j];
            #pragma unroll
            for (int k = 0; k < KB; k++) s += a[k] * fc2_w[j * KB + k];
            lg[j] = s; m = fmaxf(m, s);
        }
        float den = 0.f;
        #pragma unroll
        for (int j = 0; j < KB; j++) { lg[j] = expf(lg[j] - m); den += lg[j]; }
        float inv = 1.f / den;
        #pragma unroll
        for (int j = 0; j < KB; j++) s_att[j] = lg[j] * inv;
    }
    __syncthreads();
    int r = blockIdx.x * 256 + tid;
    float s = 0.f;
    #pragma unroll
    for (int k = 0; k < KB; k++) s += s_att[k] * weight[(size_t)k * PER_B + r];
    g_wg[(size_t)b * PER_B + r] = to_tf32(s);
    int o = r / KTOT, rem = r - o * KTOT;
    int i = rem / 25, t = rem - i * 25;
    out_wret[((size_t)(b * DIM + o) * 25 + t) * DIM + i] = s;   // exact f32
    if (blockIdx.x == 0 && tid < DIM) {
        float sb = 0.f;
        #pragma unroll
        for (int k = 0; k < KB; k++) sb += s_att[k] * bias[k * DIM + tid];
        g_aggb[b * DIM + tid] = sb;
    }
}

// ------------------------------------------------- tf32 mma.sync implicit-GEMM conv
// CTA=(oy-pair, b): D[256px,64co] = A_im2col[256,1600] x W[64,1600]^T. 8 warps 64x32.
// A staged source-aligned (dx folded into s_off) -> aligned LDG.128/STS.128 staging.
__global__ __launch_bounds__(256) void conv_mma_kernel(float* __restrict__ out) {
    extern __shared__ float sm[];
    int tid = threadIdx.x, lane = tid & 31, wid = tid >> 5;
    int wm = wid & 3, wn = wid >> 2;
    int oy0 = blockIdx.x * 2, b = blockIdx.y;

    const float* xpb = g_xp + (size_t)b * 4 * DIM * 16384;
    const float* wgb = g_wg + (size_t)b * PER_B;

    int rowj = tid >> 2, u = tid & 3;          // A stage: 64 rows x 4 threads
    int lk = rowj >> 1, q = rowj & 1;
    int bco = tid >> 2, bkq = tid & 3;         // B stage: 64 co x 4 threads

    float acc[4][4][4];
    #pragma unroll
    for (int mt = 0; mt < 4; mt++)
        #pragma unroll
        for (int nt = 0; nt < 4; nt++)
            #pragma unroll
            for (int r2 = 0; r2 < 4; r2++) acc[mt][nt][r2] = 0.f;

    int g = lane >> 2, cl = lane & 3;
    int qoff = (wm >> 1) * AROW;
    int oxb = (wm & 1) * 64 + g;

    auto stage = [&](int c, int buf) {
        float* sA = sm + (buf ? OFF_A1 : OFF_A0);
        float* sB = sm + (buf ? OFF_B1 : OFF_B0);
        int*   sT = (int*)(sm + (buf ? OFF_T1 : OFF_T0));
        int k = c * KC + lk;
        int meta = g_ktab[k];
        int ryo = ((meta >> 4) & 15) - 1;
        int dx  = (meta & 15) - 1;
        int ry = oy0 + q + ryo;
        float* row = sA + rowj * AROW;
        if (u == 0) {
            row[3] = 0.f;
            if (q == 0) sT[lk] = (2 * lk) * AROW + 4 + dx;
        }
        if (u == 3) row[132] = 0.f;
        bool ok = (unsigned)ry < 128u;
        const float4* src = (const float4*)(xpb + (meta >> 8) * 16384 + ry * 128);
        #pragma unroll
        for (int i = 0; i < 8; i++) {
            int idx = i * 4 + u;
            float4 v = ok ? src[idx] : make_float4(0.f, 0.f, 0.f, 0.f);
            *(float4*)(row + 4 + idx * 4) = v;
        }
        // B: 64co x 32k
        const float4* wr = (const float4*)(wgb + (size_t)bco * KTOT + c * KC + bkq * 8);
        float4 w0 = wr[0], w1 = wr[1];
        float* db = sB + bco * BSTRIDE + bkq * 8;
        db[0] = w0.x; db[1] = w0.y; db[2] = w0.z; db[3] = w0.w;
        db[4] = w1.x; db[5] = w1.y; db[6] = w1.z; db[7] = w1.w;
    };

    auto consume = [&](int buf) {
        const float* sA = sm + (buf ? OFF_A1 : OFF_A0);
        const float* sB = sm + (buf ? OFF_B1 : OFF_B0);
        const int*   sT = (const int*)(sm + (buf ? OFF_T1 : OFF_T0));
        #pragma unroll
        for (int k8 = 0; k8 < 4; k8++) {
            int k0 = k8 * 8;
            int off0 = sT[k0 + cl] + qoff + oxb;
            int off4 = sT[k0 + cl + 4] + qoff + oxb;
            uint32_t a[4][4];
            #pragma unroll
            for (int mt = 0; mt < 4; mt++) {
                a[mt][0] = __float_as_uint(sA[off0 + mt * 16]);
                a[mt][1] = __float_as_uint(sA[off0 + mt * 16 + 8]);
                a[mt][2] = __float_as_uint(sA[off4 + mt * 16]);
                a[mt][3] = __float_as_uint(sA[off4 + mt * 16 + 8]);
            }
            #pragma unroll
            for (int nt = 0; nt < 4; nt++) {
                const float* bb = sB + (wn * 32 + nt * 8 + g) * BSTRIDE + k0 + cl;
                uint32_t b0 = __float_as_uint(bb[0]);
                uint32_t b1 = __float_as_uint(bb[4]);
                #pragma unroll
                for (int mt = 0; mt < 4; mt++)
                    mma_tf32(acc[mt][nt], a[mt], b0, b1);
            }
        }
    };

    stage(0, 0);
    __syncthreads();
    for (int c = 0; c < CHUNKS; c++) {
        if (c + 1 < CHUNKS) stage(c + 1, (c + 1) & 1);
        consume(c & 1);
        __syncthreads();
    }

    const float* ab = g_aggb + b * DIM;
    #pragma unroll
    for (int mt = 0; mt < 4; mt++) {
        int pxb = wm * 64 + mt * 16 + g;
        #pragma unroll
        for (int half = 0; half < 2; half++) {
            int px = pxb + half * 8;
            int qq = px >> 7, ox = px & 127;
            int oy = oy0 + qq;
            if (oy < HO && ox < WO) {
                #pragma unroll
                for (int nt = 0; nt < 4; nt++) {
                    int co = wn * 32 + nt * 8 + cl * 2;
                    float* op = out + ((size_t)(b * DIM + co)) * (HO * WO) + oy * WO + ox;
                    op[0]       = acc[mt][nt][2 * half]     + ab[co];
                    op[HO * WO] = acc[mt][nt][2 * half + 1] + ab[co + 1];
                }
            }
        }
    }
}

// ------------------------------------------------- launch
extern "C" void kernel_launch(void* const* d_in, const int* in_sizes, int n_in,
                              void* d_out, int out_size) {
    const float* x     = (const float*)d_in[0];
    const float* fc1_w = (const float*)d_in[1];
    const float* fc1_b = (const float*)d_in[2];
    const float* fc2_w = (const float*)d_in[3];
    const float* fc2_b = (const float*)d_in[4];
    const float* weight = (const float*)d_in[5];
    const float* bias  = (const float*)d_in[6];

    float* out = (float*)d_out;
    float* wret = out + (size_t)BATCH * DIM * HO * WO;

    prepass_kernel<<<BATCH * DIM, 256>>>(x);
    aggw_kernel<<<dim3(PER_B / 256, BATCH), 256>>>(fc1_w, fc1_b, fc2_w, fc2_b,
                                                   weight, bias, wret);
    cudaFuncSetAttribute(conv_mma_kernel, cudaFuncAttributeMaxDynamicSharedMemorySize,
                         SMEM_WORDS * 4);
    conv_mma_kernel<<<dim3(64, BATCH), 256, SMEM_WORDS * 4>>>(out);
}

// round 8
// speedup vs baseline: 3.3729x; 1.2430x over previous
#include <cuda_runtime.h>
#include <cstdint>

#define DIM 64
#define KB 4
#define BATCH 16
#define HIN 256
#define WIN 256
#define HO 127
#define WO 127
#define KTOT 1600
#define KC 32
#define CHUNKS 50
#define PER_B (DIM * KTOT)   // 102400

#define AROW 136             // words per row instance; data at [4..131], pads at 3/132
#define NROW 16              // distinct source rows per chunk (upper bound)
#define BSTRIDE 36
#define OFF_A0 0
#define OFF_A1 (2 * NROW * AROW)          // 4352
#define OFF_B0 (2 * OFF_A1)               // 8704
#define OFF_B1 (OFF_B0 + 64 * BSTRIDE)    // 11008
#define SMEM_WORDS (OFF_B1 + 64 * BSTRIDE)   // 13312 words = 53248 B

__device__ float g_xp[BATCH * DIM * 4 * 128 * 128];   // polyphase images (tf32)
__device__ float g_pooled[BATCH * DIM];
__device__ float g_aggb[BATCH * DIM];
__device__ float g_wg[BATCH * DIM * KTOT];            // mixed weights [b][co][k] (tf32)
__device__ int   g_taptab[KTOT];                      // word offset (q=0): slot*2*AROW+4+dx
__device__ int   g_rowtab[CHUNKS * NROW];             // plane<<8 | (ryo+1)

__device__ __forceinline__ uint32_t smem_u32(const void* p) {
    uint32_t a;
    asm("{ .reg .u64 t; cvta.to.shared.u64 t, %1; cvt.u32.u64 %0, t; }" : "=r"(a) : "l"(p));
    return a;
}
__device__ __forceinline__ float to_tf32(float v) {
    uint32_t u; asm("cvt.rna.tf32.f32 %0, %1;" : "=r"(u) : "f"(v));
    return __uint_as_float(u);
}
__device__ __forceinline__ void mma_tf32(float* d, const uint32_t* a, uint32_t b0, uint32_t b1) {
    asm volatile(
        "mma.sync.aligned.m16n8k8.row.col.f32.tf32.tf32.f32 "
        "{%0,%1,%2,%3}, {%4,%5,%6,%7}, {%8,%9}, {%0,%1,%2,%3};"
        : "+f"(d[0]), "+f"(d[1]), "+f"(d[2]), "+f"(d[3])
        : "r"(a[0]), "r"(a[1]), "r"(a[2]), "r"(a[3]), "r"(b0), "r"(b1));
}
__device__ __forceinline__ void cp16(uint32_t dst, const float* src, int sz) {
    asm volatile("cp.async.ca.shared.global [%0], [%1], 16, %2;"
                 :: "r"(dst), "l"(__cvta_generic_to_global(src)), "r"(sz) : "memory");
}

// ------------------------------------------------- prepass: polyphase split + pool + tables
__global__ void prepass_kernel(const float* __restrict__ x) {
    int bc = blockIdx.x;
    if (bc == 0 && threadIdx.x < CHUNKS) {
        int c = threadIdx.x;
        int keys[NROW];
        int n = 0;
        for (int j = 0; j < KC; j++) {
            int k = c * KC + j;
            int cin = k / 25, t = k % 25, ky = t / 5, kx = t % 5;
            int pr = (ky + 1) & 1, pc = (kx + 1) & 1;
            int ryo = (ky - 1) >> 1, dx = (kx - 1) >> 1;
            int key = ((cin * 4 + pr * 2 + pc) << 8) | (ryo + 1);
            int r = -1;
            for (int i = 0; i < n; i++) if (keys[i] == key) { r = i; break; }
            if (r < 0) { keys[n] = key; r = n++; }
            g_taptab[k] = r * 2 * AROW + 4 + dx;
        }
        for (int i = 0; i < NROW; i++)
            g_rowtab[c * NROW + i] = (i < n) ? keys[i] : 1;   // pad: plane0, ryo 0
    }
    const float2* src = (const float2*)(x + (size_t)bc * HIN * WIN);
    float* pl = g_xp + (size_t)bc * 4 * 16384;
    float s = 0.f;
    for (int i = threadIdx.x; i < 128 * 256; i += 256) {
        int iy = i >> 7, hx = i & 127;
        float2 v = src[i];
        s += v.x + v.y;
        int r = iy >> 1, pr = iy & 1;
        pl[(pr * 2 + 0) * 16384 + r * 128 + hx] = to_tf32(v.x);
        pl[(pr * 2 + 1) * 16384 + r * 128 + hx] = to_tf32(v.y);
    }
    __shared__ float red[256];
    red[threadIdx.x] = s;
    __syncthreads();
    for (int off = 128; off > 0; off >>= 1) {
        if (threadIdx.x < off) red[threadIdx.x] += red[threadIdx.x + off];
        __syncthreads();
    }
    if (threadIdx.x == 0) g_pooled[bc] = red[0] * (1.f / (HIN * WIN));
}

// ------------------------------------------------- attention + weight mix + w_ret + agg_b
__global__ void aggw_kernel(const float* __restrict__ fc1_w, const float* __restrict__ fc1_b,
                            const float* __restrict__ fc2_w, const float* __restrict__ fc2_b,
                            const float* __restrict__ weight, const float* __restrict__ bias,
                            float* __restrict__ out_wret) {
    __shared__ float s_att[KB];
    int b = blockIdx.y, tid = threadIdx.x;
    if (tid == 0) {
        float a[KB];
        #pragma unroll
        for (int k = 0; k < KB; k++) {
            float s = fc1_b[k];
            for (int c = 0; c < DIM; c++) s += g_pooled[b * DIM + c] * fc1_w[k * DIM + c];
            a[k] = fmaxf(s, 0.f);
        }
        float lg[KB], m = -1e30f;
        #pragma unroll
        for (int j = 0; j < KB; j++) {
            float s = fc2_b[j];
            #pragma unroll
            for (int k = 0; k < KB; k++) s += a[k] * fc2_w[j * KB + k];
            lg[j] = s; m = fmaxf(m, s);
        }
        float den = 0.f;
        #pragma unroll
        for (int j = 0; j < KB; j++) { lg[j] = expf(lg[j] - m); den += lg[j]; }
        float inv = 1.f / den;
        #pragma unroll
        for (int j = 0; j < KB; j++) s_att[j] = lg[j] * inv;
    }
    __syncthreads();
    int r = blockIdx.x * 256 + tid;
    float s = 0.f;
    #pragma unroll
    for (int k = 0; k < KB; k++) s += s_att[k] * weight[(size_t)k * PER_B + r];
    g_wg[(size_t)b * PER_B + r] = to_tf32(s);
    int o = r / KTOT, rem = r - o * KTOT;
    int i = rem / 25, t = rem - i * 25;
    out_wret[((size_t)(b * DIM + o) * 25 + t) * DIM + i] = s;   // exact f32
    if (blockIdx.x == 0 && tid < DIM) {
        float sb = 0.f;
        #pragma unroll
        for (int k = 0; k < KB; k++) sb += s_att[k] * bias[k * DIM + tid];
        g_aggb[b * DIM + tid] = sb;
    }
}

// ------------------------------------------------- tf32 mma.sync implicit-GEMM conv
// CTA=(oy-pair, b): D[256px,64co] = A_im2col[256,1600] x W[64,1600]^T. 8 warps 64x32.
// Row-deduped A staging (<=16 rows x 2q per 32-tap chunk) via cp.async zfill.
__global__ __launch_bounds__(256) void conv_mma_kernel(float* __restrict__ out) {
    extern __shared__ float sm[];
    int tid = threadIdx.x, lane = tid & 31, wid = tid >> 5;
    int wm = wid & 3, wn = wid >> 2;
    int oy0 = blockIdx.x * 2, b = blockIdx.y;

    const float* xpb = g_xp + (size_t)b * 4 * DIM * 16384;
    const float* wgb = g_wg + (size_t)b * PER_B;

    int j = tid >> 3;            // 0..31 row instance (r = j>>1, q = j&1)
    int rr = j >> 1, q = j & 1, u = tid & 7;
    int bco = tid >> 2, bkq = tid & 3;

    float acc[4][4][4];
    #pragma unroll
    for (int mt = 0; mt < 4; mt++)
        #pragma unroll
        for (int nt = 0; nt < 4; nt++)
            #pragma unroll
            for (int r2 = 0; r2 < 4; r2++) acc[mt][nt][r2] = 0.f;

    int g = lane >> 2, cl = lane & 3;
    int qoff = (wm >> 1) * AROW;
    int oxb = (wm & 1) * 64 + g;

    auto stage = [&](int c, int buf) {
        float* sA = sm + (buf ? OFF_A1 : OFF_A0);
        float* sB = sm + (buf ? OFF_B1 : OFF_B0);
        int meta = g_rowtab[c * NROW + rr];
        int ry = oy0 + q + ((meta & 15) - 1);
        bool ok = (unsigned)ry < 128u;
        const float* src = xpb + (meta >> 8) * 16384 + ry * 128;
        float* row = sA + j * AROW;
        if (u == 0) row[3] = 0.f;
        if (u == 7) row[132] = 0.f;
        uint32_t dstb = smem_u32(row + 4);
        int sz = ok ? 16 : 0;
        #pragma unroll
        for (int i = 0; i < 4; i++) {
            int idx = u + i * 8;
            cp16(dstb + (uint32_t)idx * 16u, src + idx * 4, sz);
        }
        const float* wsrc = wgb + (size_t)bco * KTOT + c * KC + bkq * 8;
        uint32_t bdst = smem_u32(sB + bco * BSTRIDE + bkq * 8);
        cp16(bdst, wsrc, 16);
        cp16(bdst + 16u, wsrc + 4, 16);
    };

    auto consume = [&](int c, int buf) {
        const float* sA = sm + (buf ? OFF_A1 : OFF_A0);
        const float* sB = sm + (buf ? OFF_B1 : OFF_B0);
        const int* tb = g_taptab + c * KC;
        #pragma unroll
        for (int k8 = 0; k8 < 4; k8++) {
            int k0 = k8 * 8;
            int off0 = __ldg(tb + k0 + cl) + qoff + oxb;
            int off4 = __ldg(tb + k0 + cl + 4) + qoff + oxb;
            uint32_t a[4][4];
            #pragma unroll
            for (int mt = 0; mt < 4; mt++) {
                a[mt][0] = __float_as_uint(sA[off0 + mt * 16]);
                a[mt][1] = __float_as_uint(sA[off0 + mt * 16 + 8]);
                a[mt][2] = __float_as_uint(sA[off4 + mt * 16]);
                a[mt][3] = __float_as_uint(sA[off4 + mt * 16 + 8]);
            }
            #pragma unroll
            for (int nt = 0; nt < 4; nt++) {
                const float* bb = sB + (wn * 32 + nt * 8 + g) * BSTRIDE + k0 + cl;
                uint32_t b0 = __float_as_uint(bb[0]);
                uint32_t b1 = __float_as_uint(bb[4]);
                #pragma unroll
                for (int mt = 0; mt < 4; mt++)
                    mma_tf32(acc[mt][nt], a[mt], b0, b1);
            }
        }
    };

    stage(0, 0);
    asm volatile("cp.async.commit_group;" ::: "memory");
    for (int c = 0; c < CHUNKS; c++) {
        if (c + 1 < CHUNKS) {
            stage(c + 1, (c + 1) & 1);
            asm volatile("cp.async.commit_group;" ::: "memory");
            asm volatile("cp.async.wait_group 1;" ::: "memory");
        } else {
            asm volatile("cp.async.wait_group 0;" ::: "memory");
        }
        __syncthreads();
        consume(c, c & 1);
        __syncthreads();
    }

    const float* ab = g_aggb + b * DIM;
    #pragma unroll
    for (int mt = 0; mt < 4; mt++) {
        int pxb = wm * 64 + mt * 16 + g;
        #pragma unroll
        for (int half = 0; half < 2; half++) {
            int px = pxb + half * 8;
            int qq = px >> 7, ox = px & 127;
            int oy = oy0 + qq;
            if (oy < HO && ox < WO) {
                #pragma unroll
                for (int nt = 0; nt < 4; nt++) {
                    int co = wn * 32 + nt * 8 + cl * 2;
                    float* op = out + ((size_t)(b * DIM + co)) * (HO * WO) + oy * WO + ox;
                    op[0]       = acc[mt][nt][2 * half]     + ab[co];
                    op[HO * WO] = acc[mt][nt][2 * half + 1] + ab[co + 1];
                }
            }
        }
    }
}

// ------------------------------------------------- launch
extern "C" void kernel_launch(void* const* d_in, const int* in_sizes, int n_in,
                              void* d_out, int out_size) {
    const float* x     = (const float*)d_in[0];
    const float* fc1_w = (const float*)d_in[1];
    const float* fc1_b = (const float*)d_in[2];
    const float* fc2_w = (const float*)d_in[3];
    const float* fc2_b = (const float*)d_in[4];
    const float* weight = (const float*)d_in[5];
    const float* bias  = (const float*)d_in[6];

    float* out = (float*)d_out;
    float* wret = out + (size_t)BATCH * DIM * HO * WO;

    prepass_kernel<<<BATCH * DIM, 256>>>(x);
    aggw_kernel<<<dim3(PER_B / 256, BATCH), 256>>>(fc1_w, fc1_b, fc2_w, fc2_b,
                                                   weight, bias, wret);
    cudaFuncSetAttribute(conv_mma_kernel, cudaFuncAttributeMaxDynamicSharedMemorySize,
                         SMEM_WORDS * 4);
    conv_mma_kernel<<<dim3(64, BATCH), 256, SMEM_WORDS * 4>>>(out);
}